// round 1
// baseline (speedup 1.0000x reference)
#include <cuda_runtime.h>

#define NN   4096
#define DIM  320
#define KP0  3686
#define KP1  2580

#define OFF_START (NN*DIM)
#define OFF_POOL  (2*NN*DIM)

// ---------------- scratch (static device globals; no allocation) -------------
__device__ __align__(16) float g_AX  [NN*2*DIM];
__device__ __align__(16) float g_AX2 [NN*2*DIM];
__device__ __align__(16) float g_X0  [NN*DIM];
__device__ __align__(16) float g_Xd0 [NN*DIM];
__device__ __align__(16) float g_Xp0 [KP0*DIM];
__device__ __align__(16) float g_Xd1 [KP0*DIM];
__device__ __align__(16) float g_Xp1 [KP1*DIM];
__device__ __align__(16) float g_Xb  [KP1*DIM];
__device__ __align__(16) float g_Xu  [KP0*DIM];
__device__ __align__(16) float g_Xcat[NN*2*DIM];
__device__ float g_scores[NN];
__device__ int   g_idx0[NN];
__device__ float g_val0[NN];
__device__ int   g_idx1[NN];
__device__ float g_val1[NN];
__device__ int   g_idx01[KP1];

// ---------------- generic SGEMM: C[M,F] = gather(A) @ B ----------------------
// C[m,f] = sum_k A[ ridx?ridx[m]:m , cidx?cidx[k]:k ] * B[k,f]
// BM=BN=64, BK=16, 256 threads, 4x4 per thread. F must be a multiple of 64.
__global__ void gemm64(const float* __restrict__ A, int lda,
                       const int* __restrict__ ridx, const int* __restrict__ cidx,
                       const float* __restrict__ B, int ldb,
                       float* __restrict__ C, int ldc,
                       int M, int K)
{
    const int BM = 64, BN = 64, BK = 16, PAD = 4;
    __shared__ float As[BK][BM + PAD];
    __shared__ float Bs[BK][BN + PAD];

    int tid = threadIdx.x;
    int tx = tid & 15, ty = tid >> 4;
    int bm0 = blockIdx.y * BM;
    int bn0 = blockIdx.x * BN;

    int am = tid >> 2;          // 0..63 : m within tile (A load)
    int ak = (tid & 3) * 4;     // 0,4,8,12 : k within tile (A load)
    int gm = bm0 + am;
    int arow = -1;
    if (gm < M) arow = ridx ? ridx[gm] : gm;

    int bk = tid >> 4;          // 0..15 : k within tile (B load)
    int bn = (tid & 15) * 4;    // col within tile (B load)

    float acc[4][4];
#pragma unroll
    for (int i = 0; i < 4; i++)
#pragma unroll
        for (int j = 0; j < 4; j++) acc[i][j] = 0.f;

    for (int k0 = 0; k0 < K; k0 += BK) {
        // ---- A tile -> As[k][m]
        if (arow >= 0) {
            if (!cidx && (k0 + BK) <= K) {
                float4 v = *reinterpret_cast<const float4*>(A + (size_t)arow * lda + k0 + ak);
                As[ak + 0][am] = v.x; As[ak + 1][am] = v.y;
                As[ak + 2][am] = v.z; As[ak + 3][am] = v.w;
            } else {
#pragma unroll
                for (int i = 0; i < 4; i++) {
                    int k = k0 + ak + i;
                    float v = 0.f;
                    if (k < K) { int c = cidx ? cidx[k] : k; v = A[(size_t)arow * lda + c]; }
                    As[ak + i][am] = v;
                }
            }
        } else {
#pragma unroll
            for (int i = 0; i < 4; i++) As[ak + i][am] = 0.f;
        }
        // ---- B tile -> Bs[k][n]
        {
            int k = k0 + bk;
            if (k < K) {
                float4 v = *reinterpret_cast<const float4*>(B + (size_t)k * ldb + bn0 + bn);
                Bs[bk][bn + 0] = v.x; Bs[bk][bn + 1] = v.y;
                Bs[bk][bn + 2] = v.z; Bs[bk][bn + 3] = v.w;
            } else {
                Bs[bk][bn + 0] = 0.f; Bs[bk][bn + 1] = 0.f;
                Bs[bk][bn + 2] = 0.f; Bs[bk][bn + 3] = 0.f;
            }
        }
        __syncthreads();
#pragma unroll
        for (int kk = 0; kk < BK; kk++) {
            float4 a = *reinterpret_cast<const float4*>(&As[kk][ty * 4]);
            float4 b = *reinterpret_cast<const float4*>(&Bs[kk][tx * 4]);
            float av[4] = {a.x, a.y, a.z, a.w};
            float bv[4] = {b.x, b.y, b.z, b.w};
#pragma unroll
            for (int i = 0; i < 4; i++)
#pragma unroll
                for (int j = 0; j < 4; j++) acc[i][j] += av[i] * bv[j];
        }
        __syncthreads();
    }
#pragma unroll
    for (int i = 0; i < 4; i++) {
        int m = bm0 + ty * 4 + i;
        if (m < M) {
            float4 v = make_float4(acc[i][0], acc[i][1], acc[i][2], acc[i][3]);
            *reinterpret_cast<float4*>(C + (size_t)m * ldc + bn0 + tx * 4) = v;
        }
    }
}

// ---------------- pool_out = X @ X^T with unit diagonal ----------------------
__global__ void pool_gemm(const float* __restrict__ X, float* __restrict__ out, int n)
{
    const int BM = 64, BK = 16, PAD = 4;
    __shared__ float As[BK][BM + PAD];
    __shared__ float Bs[BK][BM + PAD];

    int tid = threadIdx.x;
    int tx = tid & 15, ty = tid >> 4;
    int bm0 = blockIdx.y * BM;
    int bn0 = blockIdx.x * BM;
    int am = tid >> 2;
    int ak = (tid & 3) * 4;

    float acc[4][4];
#pragma unroll
    for (int i = 0; i < 4; i++)
#pragma unroll
        for (int j = 0; j < 4; j++) acc[i][j] = 0.f;

    for (int k0 = 0; k0 < DIM; k0 += BK) {
        int gm = bm0 + am;
        if (gm < n) {
            float4 v = *reinterpret_cast<const float4*>(X + (size_t)gm * DIM + k0 + ak);
            As[ak + 0][am] = v.x; As[ak + 1][am] = v.y; As[ak + 2][am] = v.z; As[ak + 3][am] = v.w;
        } else {
#pragma unroll
            for (int i = 0; i < 4; i++) As[ak + i][am] = 0.f;
        }
        int gn = bn0 + am;
        if (gn < n) {
            float4 v = *reinterpret_cast<const float4*>(X + (size_t)gn * DIM + k0 + ak);
            Bs[ak + 0][am] = v.x; Bs[ak + 1][am] = v.y; Bs[ak + 2][am] = v.z; Bs[ak + 3][am] = v.w;
        } else {
#pragma unroll
            for (int i = 0; i < 4; i++) Bs[ak + i][am] = 0.f;
        }
        __syncthreads();
#pragma unroll
        for (int kk = 0; kk < BK; kk++) {
            float4 a = *reinterpret_cast<const float4*>(&As[kk][ty * 4]);
            float4 b = *reinterpret_cast<const float4*>(&Bs[kk][tx * 4]);
            float av[4] = {a.x, a.y, a.z, a.w};
            float bv[4] = {b.x, b.y, b.z, b.w};
#pragma unroll
            for (int i = 0; i < 4; i++)
#pragma unroll
                for (int j = 0; j < 4; j++) acc[i][j] += av[i] * bv[j];
        }
        __syncthreads();
    }
#pragma unroll
    for (int i = 0; i < 4; i++) {
        int gi = bm0 + ty * 4 + i;
        if (gi >= n) continue;
#pragma unroll
        for (int j = 0; j < 4; j++) {
            int gj = bn0 + tx * 4 + j;
            if (gj < n) out[(size_t)gi * n + gj] = (gi == gj) ? 1.0f : acc[i][j];
        }
    }
}

// ---------------- bias + ReLU (+residual), up to two destinations ------------
__global__ void epilogue(const float* __restrict__ T, const float* __restrict__ bias,
                         const float* __restrict__ R,
                         float* __restrict__ d1, int ld1,
                         float* __restrict__ d2, int ld2, int n)
{
    int i = blockIdx.x * blockDim.x + threadIdx.x;
    if (i >= n * DIM) return;
    int r = i / DIM, c = i - r * DIM;
    float v = T[i] + bias[c];
    v = v > 0.f ? v : 0.f;
    if (R) v += R[i];
    d1[(size_t)r * ld1 + c] = v;
    if (d2) d2[(size_t)r * ld2 + c] = v;
}

// ---------------- pooling scores: sigmoid((X . pw + pb)/100) -----------------
__global__ void scores_kernel(const float* __restrict__ X, int n,
                              const float* __restrict__ pw, const float* __restrict__ pb,
                              float* __restrict__ out)
{
    int row = blockIdx.x * 8 + (threadIdx.x >> 5);
    int lane = threadIdx.x & 31;
    if (row >= n) return;
    float s = 0.f;
    for (int c = lane; c < DIM; c += 32) s += X[(size_t)row * DIM + c] * pw[c];
#pragma unroll
    for (int o = 16; o > 0; o >>= 1) s += __shfl_down_sync(0xffffffffu, s, o);
    if (lane == 0) {
        float z = (s + pb[0]) * 0.01f;
        out[row] = 1.0f / (1.0f + expf(-z));
    }
}

// ---------------- exact top-k via full bitonic sort (desc score, asc idx) ----
__global__ void topk_sort(const float* __restrict__ scores, int n,
                          int* __restrict__ idx_out, float* __restrict__ val_out)
{
    __shared__ unsigned long long keys[4096];
    int tid = threadIdx.x;  // 1024 threads
    for (int i = tid; i < 4096; i += 1024) {
        unsigned long long k = 0ull;
        if (i < n) {
            unsigned int fb = __float_as_uint(scores[i]);  // scores in [0,1] -> monotone bits
            k = ((unsigned long long)fb << 12) | (unsigned int)(4095 - i);
        }
        keys[i] = k;
    }
    __syncthreads();
    for (int k = 2; k <= 4096; k <<= 1) {
        for (int j = k >> 1; j > 0; j >>= 1) {
            for (int t = tid; t < 4096; t += 1024) {
                int ixj = t ^ j;
                if (ixj > t) {
                    bool desc = ((t & k) == 0);
                    unsigned long long a = keys[t], b = keys[ixj];
                    if ((a < b) == desc) { keys[t] = b; keys[ixj] = a; }
                }
            }
            __syncthreads();
        }
    }
    for (int i = tid; i < 4096; i += 1024) {
        unsigned long long kk = keys[i];
        idx_out[i] = 4095 - (int)(kk & 0xFFFull);
        val_out[i] = __uint_as_float((unsigned int)(kk >> 12));
    }
}

__global__ void gather_scale(const float* __restrict__ X, const int* __restrict__ idx,
                             const float* __restrict__ vals, float* __restrict__ out, int kn)
{
    int i = blockIdx.x * 256 + threadIdx.x;
    if (i >= kn * DIM) return;
    int r = i / DIM, c = i - r * DIM;
    out[i] = X[(size_t)idx[r] * DIM + c] * vals[r];
}

__global__ void compose_idx(const int* __restrict__ a, const int* __restrict__ b,
                            int* __restrict__ out, int n)
{
    int i = blockIdx.x * 256 + threadIdx.x;
    if (i < n) out[i] = a[b[i]];
}

// -----------------------------------------------------------------------------
extern "C" void kernel_launch(void* const* d_in, const int* in_sizes, int n_in,
                              void* d_out, int out_size)
{
    const float* A       = (const float*)d_in[0];
    const float* X       = (const float*)d_in[1];
    const float* w_start = (const float*)d_in[2];  const float* b_start  = (const float*)d_in[3];
    const float* w_down0 = (const float*)d_in[4];  const float* b_down0  = (const float*)d_in[5];
    const float* w_down1 = (const float*)d_in[6];  const float* b_down1  = (const float*)d_in[7];
    const float* p_w0    = (const float*)d_in[8];  const float* p_b0     = (const float*)d_in[9];
    const float* p_w1    = (const float*)d_in[10]; const float* p_b1     = (const float*)d_in[11];
    const float* w_bottom= (const float*)d_in[12]; const float* b_bottom = (const float*)d_in[13];
    const float* w_up0   = (const float*)d_in[14]; const float* b_up0    = (const float*)d_in[15];
    const float* w_up1   = (const float*)d_in[16]; const float* b_up1    = (const float*)d_in[17];
    const float* w_end   = (const float*)d_in[18]; const float* b_end    = (const float*)d_in[19];
    float* out = (float*)d_out;

    float *AX, *AX2, *X0, *Xd0, *Xp0, *Xd1, *Xp1, *Xb, *Xu, *Xcat, *sc, *v0, *v1;
    int *i0, *i1, *i01;
    cudaGetSymbolAddress((void**)&AX,   g_AX);
    cudaGetSymbolAddress((void**)&AX2,  g_AX2);
    cudaGetSymbolAddress((void**)&X0,   g_X0);
    cudaGetSymbolAddress((void**)&Xd0,  g_Xd0);
    cudaGetSymbolAddress((void**)&Xp0,  g_Xp0);
    cudaGetSymbolAddress((void**)&Xd1,  g_Xd1);
    cudaGetSymbolAddress((void**)&Xp1,  g_Xp1);
    cudaGetSymbolAddress((void**)&Xb,   g_Xb);
    cudaGetSymbolAddress((void**)&Xu,   g_Xu);
    cudaGetSymbolAddress((void**)&Xcat, g_Xcat);
    cudaGetSymbolAddress((void**)&sc,   g_scores);
    cudaGetSymbolAddress((void**)&i0,   g_idx0);
    cudaGetSymbolAddress((void**)&v0,   g_val0);
    cudaGetSymbolAddress((void**)&i1,   g_idx1);
    cudaGetSymbolAddress((void**)&v1,   g_val1);
    cudaGetSymbolAddress((void**)&i01,  g_idx01);

    auto grid = [](int M, int F) { return dim3((unsigned)(F / 64), (unsigned)((M + 63) / 64)); };
    auto eg = [](int n) { return (unsigned)((n * DIM + 255) / 256); };

    // ---- X0 = relu((A@X)@w_start + b)  (also -> out_start and Xcat right half)
    gemm64<<<grid(NN, DIM), 256>>>(A, NN, nullptr, nullptr, X, DIM, AX, DIM, NN, NN);
    gemm64<<<grid(NN, DIM), 256>>>(AX, DIM, nullptr, nullptr, w_start, DIM, AX2, DIM, NN, DIM);
    epilogue<<<eg(NN), 256>>>(AX2, b_start, nullptr, X0, DIM, Xcat + DIM, 2 * DIM, NN);
    cudaMemcpyAsync(out + OFF_START, X0, (size_t)NN * DIM * sizeof(float),
                    cudaMemcpyDeviceToDevice, 0);

    // ---- Xd0 = gcn(A, X0, w_down0)
    gemm64<<<grid(NN, DIM), 256>>>(A, NN, nullptr, nullptr, X0, DIM, AX, DIM, NN, NN);
    gemm64<<<grid(NN, DIM), 256>>>(AX, DIM, nullptr, nullptr, w_down0, DIM, AX2, DIM, NN, DIM);
    epilogue<<<eg(NN), 256>>>(AX2, b_down0, nullptr, Xd0, DIM, nullptr, 0, NN);

    // ---- pool 0
    scores_kernel<<<(NN + 7) / 8, 256>>>(Xd0, NN, p_w0, p_b0, sc);
    topk_sort<<<1, 1024>>>(sc, NN, i0, v0);
    gather_scale<<<(KP0 * DIM + 255) / 256, 256>>>(Xd0, i0, v0, Xp0, KP0);

    // ---- Xd1 = gcn(A1, Xp0, w_down1)   (A1 gathered on the fly)
    gemm64<<<grid(KP0, DIM), 256>>>(A, NN, i0, i0, Xp0, DIM, AX, DIM, KP0, KP0);
    gemm64<<<grid(KP0, DIM), 256>>>(AX, DIM, nullptr, nullptr, w_down1, DIM, AX2, DIM, KP0, DIM);
    epilogue<<<eg(KP0), 256>>>(AX2, b_down1, nullptr, Xd1, DIM, nullptr, 0, KP0);

    // ---- pool 1
    scores_kernel<<<(KP0 + 7) / 8, 256>>>(Xd1, KP0, p_w1, p_b1, sc);
    topk_sort<<<1, 1024>>>(sc, KP0, i1, v1);
    gather_scale<<<(KP1 * DIM + 255) / 256, 256>>>(Xd1, i1, v1, Xp1, KP1);
    compose_idx<<<(KP1 + 255) / 256, 256>>>(i0, i1, i01, KP1);

    // ---- bottom: Xb = gcn(A2, Xp1, w_bottom)
    gemm64<<<grid(KP1, DIM), 256>>>(A, NN, i01, i01, Xp1, DIM, AX, DIM, KP1, KP1);
    gemm64<<<grid(KP1, DIM), 256>>>(AX, DIM, nullptr, nullptr, w_bottom, DIM, AX2, DIM, KP1, DIM);
    epilogue<<<eg(KP1), 256>>>(AX2, b_bottom, nullptr, Xb, DIM, nullptr, 0, KP1);

    // ---- up 0: Xu = gcn(A1, scatter(Xb), w_up0) + Xd1   (scatter folded into K-gather)
    gemm64<<<grid(KP0, DIM), 256>>>(A, NN, i0, i01, Xb, DIM, AX, DIM, KP0, KP1);
    gemm64<<<grid(KP0, DIM), 256>>>(AX, DIM, nullptr, nullptr, w_up0, DIM, AX2, DIM, KP0, DIM);
    epilogue<<<eg(KP0), 256>>>(AX2, b_up0, Xd1, Xu, DIM, nullptr, 0, KP0);

    // ---- up 1: Xu2 = gcn(A, scatter(Xu), w_up1) + Xd0  -> Xcat left half
    gemm64<<<grid(NN, DIM), 256>>>(A, NN, nullptr, i0, Xu, DIM, AX, DIM, NN, KP0);
    gemm64<<<grid(NN, DIM), 256>>>(AX, DIM, nullptr, nullptr, w_up1, DIM, AX2, DIM, NN, DIM);
    epilogue<<<eg(NN), 256>>>(AX2, b_up1, Xd0, Xcat, 2 * DIM, nullptr, 0, NN);

    // ---- end: Xout = gcn(A, Xcat, w_end)
    gemm64<<<grid(NN, 2 * DIM), 256>>>(A, NN, nullptr, nullptr, Xcat, 2 * DIM, AX, 2 * DIM, NN, NN);
    gemm64<<<grid(NN, DIM), 256>>>(AX, 2 * DIM, nullptr, nullptr, w_end, DIM, AX2, DIM, NN, 2 * DIM);
    epilogue<<<eg(NN), 256>>>(AX2, b_end, nullptr, out, DIM, nullptr, 0, NN);

    // ---- pool_out = Xp0 @ Xp0^T, diag = 1
    pool_gemm<<<dim3((KP0 + 63) / 64, (KP0 + 63) / 64), 256>>>(Xp0, out + OFF_POOL, KP0);
}

// round 2
// speedup vs baseline: 1.0414x; 1.0414x over previous
#include <cuda_runtime.h>

#define NN   4096
#define DIM  320
#define KP0  3686
#define KP1  2580
#define KP0P 3696   // KP0 padded to multiple of 16
#define KP1P 2592   // KP1 padded to multiple of 16

#define OFF_START (NN*DIM)
#define OFF_POOL  (2*NN*DIM)

// ---------------- scratch (static device globals; no allocation) -------------
__device__ __align__(16) float g_AX   [NN*DIM];
__device__ __align__(16) float g_AX2  [NN*DIM];
__device__ __align__(16) float g_X0   [NN*DIM];
__device__ __align__(16) float g_Xd0  [NN*DIM];
__device__ __align__(16) float g_Xp0  [KP0P*DIM];
__device__ __align__(16) float g_Xd1  [KP0*DIM];
__device__ __align__(16) float g_Xp1  [KP1P*DIM];
__device__ __align__(16) float g_Xb   [KP1P*DIM];
__device__ __align__(16) float g_Xu   [KP0P*DIM];
__device__ __align__(16) float g_Xcat [NN*2*DIM];
__device__ __align__(16) float g_AXcat[NN*2*DIM];
__device__ __align__(16) float g_AB1  [(size_t)KP0*KP0P];
__device__ __align__(16) float g_AB2  [(size_t)KP1*KP1P];
__device__ __align__(16) float g_ABu0 [(size_t)KP0*KP1P];
__device__ __align__(16) float g_ABu1 [(size_t)NN*KP0P];
__device__ float g_scores[NN];
__device__ int   g_idx0[NN];
__device__ float g_val0[NN];
__device__ int   g_idx1[NN];
__device__ float g_val1[NN];
__device__ int   g_idx01[KP1];

typedef unsigned long long u64;

__device__ __forceinline__ void ffma2(u64& c, u64 a, u64 b) {
    asm("fma.rn.f32x2 %0, %1, %2, %0;" : "+l"(c) : "l"(a), "l"(b));
}
__device__ __forceinline__ u64 dup2(float x) {
    u64 r;
    asm("mov.b64 %0, {%1, %1};" : "=l"(r) : "f"(x));
    return r;
}

// ---------------- dense SGEMM via packed f32x2 -------------------------------
// C[M x (gridDim.x*64)] = A[M x K] @ B[K x *]; K % 16 == 0; cols multiple of 64.
// BM=64, BN=64, BK=16, 128 threads, 8x4 per thread (cols packed as f32x2).
__global__ void gemm_f2(const float* __restrict__ A, int lda,
                        const float* __restrict__ B, int ldb,
                        float* __restrict__ C, int ldc,
                        int M, int K)
{
    const int BM = 64, BN = 64, BK = 16;
    __shared__ u64   As2[BK][BM];   // duplicated pairs {v,v}
    __shared__ float Bs [BK][BN];

    int tid = threadIdx.x;
    int tx = tid & 15;              // cols tx*4
    int ty = tid >> 4;              // rows ty*8
    int bm0 = blockIdx.y * BM;
    int bn0 = blockIdx.x * BN;

    // A loader: 64 rows x 16 k / 128 thr -> 8 floats each
    int a_r = tid >> 1;
    int a_k = (tid & 1) * 8;
    int a_gm = bm0 + a_r;
    const float* Arow = (a_gm < M) ? (A + (size_t)a_gm * lda) : 0;

    // B loader: 16 rows x 64 cols / 128 thr -> 8 floats each
    int b_k = tid >> 3;
    int b_n = (tid & 7) * 8;
    const float* Bbase = B + (size_t)b_k * ldb + bn0 + b_n;

    u64 acc[8][2];
#pragma unroll
    for (int i = 0; i < 8; i++) { acc[i][0] = 0ull; acc[i][1] = 0ull; }

    float ra[8], rb[8];
    // prefetch first tiles
    {
        if (Arow) {
            float4 v0 = *reinterpret_cast<const float4*>(Arow + a_k);
            float4 v1 = *reinterpret_cast<const float4*>(Arow + a_k + 4);
            ra[0]=v0.x; ra[1]=v0.y; ra[2]=v0.z; ra[3]=v0.w;
            ra[4]=v1.x; ra[5]=v1.y; ra[6]=v1.z; ra[7]=v1.w;
        } else {
#pragma unroll
            for (int i = 0; i < 8; i++) ra[i] = 0.f;
        }
        float4 w0 = *reinterpret_cast<const float4*>(Bbase);
        float4 w1 = *reinterpret_cast<const float4*>(Bbase + 4);
        rb[0]=w0.x; rb[1]=w0.y; rb[2]=w0.z; rb[3]=w0.w;
        rb[4]=w1.x; rb[5]=w1.y; rb[6]=w1.z; rb[7]=w1.w;
    }

    for (int k0 = 0; k0 < K; k0 += BK) {
        // store staged tiles
#pragma unroll
        for (int i = 0; i < 8; i++) As2[a_k + i][a_r] = dup2(ra[i]);
#pragma unroll
        for (int i = 0; i < 8; i++) Bs[b_k][b_n + i] = rb[i];
        __syncthreads();

        // prefetch next tiles
        if (k0 + BK < K) {
            if (Arow) {
                const float* p = Arow + k0 + BK + a_k;
                float4 v0 = *reinterpret_cast<const float4*>(p);
                float4 v1 = *reinterpret_cast<const float4*>(p + 4);
                ra[0]=v0.x; ra[1]=v0.y; ra[2]=v0.z; ra[3]=v0.w;
                ra[4]=v1.x; ra[5]=v1.y; ra[6]=v1.z; ra[7]=v1.w;
            }
            const float* q = Bbase + (size_t)(k0 + BK) * ldb;
            float4 w0 = *reinterpret_cast<const float4*>(q);
            float4 w1 = *reinterpret_cast<const float4*>(q + 4);
            rb[0]=w0.x; rb[1]=w0.y; rb[2]=w0.z; rb[3]=w0.w;
            rb[4]=w1.x; rb[5]=w1.y; rb[6]=w1.z; rb[7]=w1.w;
        }

#pragma unroll
        for (int kk = 0; kk < BK; kk++) {
            ulonglong2 b2 = *reinterpret_cast<const ulonglong2*>(&Bs[kk][tx * 4]);
            ulonglong2 a01 = *reinterpret_cast<const ulonglong2*>(&As2[kk][ty * 8 + 0]);
            ulonglong2 a23 = *reinterpret_cast<const ulonglong2*>(&As2[kk][ty * 8 + 2]);
            ulonglong2 a45 = *reinterpret_cast<const ulonglong2*>(&As2[kk][ty * 8 + 4]);
            ulonglong2 a67 = *reinterpret_cast<const ulonglong2*>(&As2[kk][ty * 8 + 6]);
            ffma2(acc[0][0], a01.x, b2.x); ffma2(acc[0][1], a01.x, b2.y);
            ffma2(acc[1][0], a01.y, b2.x); ffma2(acc[1][1], a01.y, b2.y);
            ffma2(acc[2][0], a23.x, b2.x); ffma2(acc[2][1], a23.x, b2.y);
            ffma2(acc[3][0], a23.y, b2.x); ffma2(acc[3][1], a23.y, b2.y);
            ffma2(acc[4][0], a45.x, b2.x); ffma2(acc[4][1], a45.x, b2.y);
            ffma2(acc[5][0], a45.y, b2.x); ffma2(acc[5][1], a45.y, b2.y);
            ffma2(acc[6][0], a67.x, b2.x); ffma2(acc[6][1], a67.x, b2.y);
            ffma2(acc[7][0], a67.y, b2.x); ffma2(acc[7][1], a67.y, b2.y);
        }
        __syncthreads();
    }

#pragma unroll
    for (int i = 0; i < 8; i++) {
        int m = bm0 + ty * 8 + i;
        if (m < M) {
            ulonglong2 v; v.x = acc[i][0]; v.y = acc[i][1];
            *reinterpret_cast<ulonglong2*>(C + (size_t)m * ldc + bn0 + tx * 4) = v;
        }
    }
}

// ---------------- pool_out = X @ X^T (triangular, mirrored), diag = 1 --------
__global__ void pool_gemm(const float* __restrict__ X, float* __restrict__ out, int n)
{
    const int BM = 64, BK = 16;
    int bm0 = blockIdx.y * BM;
    int bn0 = blockIdx.x * BM;
    if (bn0 < bm0) return;   // triangular

    __shared__ u64   As2[BK][BM];
    __shared__ float Bs [BK][BM];

    int tid = threadIdx.x;
    int tx = tid & 15;
    int ty = tid >> 4;

    int l_r = tid >> 1;              // 0..63
    int l_k = (tid & 1) * 8;
    int a_gm = bm0 + l_r;
    int b_gn = bn0 + l_r;
    const float* Arow = (a_gm < n) ? (X + (size_t)a_gm * DIM) : 0;
    const float* Brow = (b_gn < n) ? (X + (size_t)b_gn * DIM) : 0;

    u64 acc[8][2];
#pragma unroll
    for (int i = 0; i < 8; i++) { acc[i][0] = 0ull; acc[i][1] = 0ull; }

    for (int k0 = 0; k0 < DIM; k0 += BK) {
        if (Arow) {
            float4 v0 = *reinterpret_cast<const float4*>(Arow + k0 + l_k);
            float4 v1 = *reinterpret_cast<const float4*>(Arow + k0 + l_k + 4);
            As2[l_k+0][l_r]=dup2(v0.x); As2[l_k+1][l_r]=dup2(v0.y);
            As2[l_k+2][l_r]=dup2(v0.z); As2[l_k+3][l_r]=dup2(v0.w);
            As2[l_k+4][l_r]=dup2(v1.x); As2[l_k+5][l_r]=dup2(v1.y);
            As2[l_k+6][l_r]=dup2(v1.z); As2[l_k+7][l_r]=dup2(v1.w);
        } else {
#pragma unroll
            for (int i = 0; i < 8; i++) As2[l_k + i][l_r] = 0ull;
        }
        if (Brow) {
            float4 v0 = *reinterpret_cast<const float4*>(Brow + k0 + l_k);
            float4 v1 = *reinterpret_cast<const float4*>(Brow + k0 + l_k + 4);
            Bs[l_k+0][l_r]=v0.x; Bs[l_k+1][l_r]=v0.y; Bs[l_k+2][l_r]=v0.z; Bs[l_k+3][l_r]=v0.w;
            Bs[l_k+4][l_r]=v1.x; Bs[l_k+5][l_r]=v1.y; Bs[l_k+6][l_r]=v1.z; Bs[l_k+7][l_r]=v1.w;
        } else {
#pragma unroll
            for (int i = 0; i < 8; i++) Bs[l_k + i][l_r] = 0.f;
        }
        __syncthreads();
#pragma unroll
        for (int kk = 0; kk < BK; kk++) {
            ulonglong2 b2 = *reinterpret_cast<const ulonglong2*>(&Bs[kk][tx * 4]);
            ulonglong2 a01 = *reinterpret_cast<const ulonglong2*>(&As2[kk][ty * 8 + 0]);
            ulonglong2 a23 = *reinterpret_cast<const ulonglong2*>(&As2[kk][ty * 8 + 2]);
            ulonglong2 a45 = *reinterpret_cast<const ulonglong2*>(&As2[kk][ty * 8 + 4]);
            ulonglong2 a67 = *reinterpret_cast<const ulonglong2*>(&As2[kk][ty * 8 + 6]);
            ffma2(acc[0][0], a01.x, b2.x); ffma2(acc[0][1], a01.x, b2.y);
            ffma2(acc[1][0], a01.y, b2.x); ffma2(acc[1][1], a01.y, b2.y);
            ffma2(acc[2][0], a23.x, b2.x); ffma2(acc[2][1], a23.x, b2.y);
            ffma2(acc[3][0], a23.y, b2.x); ffma2(acc[3][1], a23.y, b2.y);
            ffma2(acc[4][0], a45.x, b2.x); ffma2(acc[4][1], a45.x, b2.y);
            ffma2(acc[5][0], a45.y, b2.x); ffma2(acc[5][1], a45.y, b2.y);
            ffma2(acc[6][0], a67.x, b2.x); ffma2(acc[6][1], a67.x, b2.y);
            ffma2(acc[7][0], a67.y, b2.x); ffma2(acc[7][1], a67.y, b2.y);
        }
        __syncthreads();
    }

#pragma unroll
    for (int i = 0; i < 8; i++) {
        int gi = bm0 + ty * 8 + i;
        if (gi >= n) continue;
        float f[4];
        *reinterpret_cast<ulonglong2*>(f) = *reinterpret_cast<ulonglong2*>(&acc[i][0]);
#pragma unroll
        for (int j = 0; j < 4; j++) {
            int gj = bn0 + tx * 4 + j;
            if (gj < n) {
                float v = (gi == gj) ? 1.0f : f[j];
                out[(size_t)gi * n + gj] = v;
                out[(size_t)gj * n + gi] = v;
            }
        }
    }
}

// ---------------- gather materialization of sub-adjacency --------------------
// dst[m,k] = (k < Ksub) ? A[ridx?ridx[m]:m, cidx[k]] : 0
__global__ void gatherA(float* __restrict__ dst, int ldd,
                        const float* __restrict__ A,
                        const int* __restrict__ ridx, const int* __restrict__ cidx,
                        int M, int Ksub, int Kpad)
{
    int k = blockIdx.x * 256 + threadIdx.x;
    int m = blockIdx.y;
    if (k >= Kpad || m >= M) return;
    float v = 0.f;
    if (k < Ksub) {
        int r = ridx ? ridx[m] : m;
        v = __ldg(&A[(size_t)r * NN + cidx[k]]);
    }
    dst[(size_t)m * ldd + k] = v;
}

// ---------------- bias + ReLU (+residual), up to two destinations ------------
__global__ void epilogue(const float* __restrict__ T, const float* __restrict__ bias,
                         const float* __restrict__ R,
                         float* __restrict__ d1, int ld1,
                         float* __restrict__ d2, int ld2, int n)
{
    int i = blockIdx.x * blockDim.x + threadIdx.x;
    if (i >= n * DIM) return;
    int r = i / DIM, c = i - r * DIM;
    float v = T[i] + bias[c];
    v = v > 0.f ? v : 0.f;
    if (R) v += R[i];
    d1[(size_t)r * ld1 + c] = v;
    if (d2) d2[(size_t)r * ld2 + c] = v;
}

// ---------------- pooling scores: sigmoid((X . pw + pb)/100) -----------------
__global__ void scores_kernel(const float* __restrict__ X, int n,
                              const float* __restrict__ pw, const float* __restrict__ pb,
                              float* __restrict__ out)
{
    int row = blockIdx.x * 8 + (threadIdx.x >> 5);
    int lane = threadIdx.x & 31;
    if (row >= n) return;
    float s = 0.f;
    for (int c = lane; c < DIM; c += 32) s += X[(size_t)row * DIM + c] * pw[c];
#pragma unroll
    for (int o = 16; o > 0; o >>= 1) s += __shfl_down_sync(0xffffffffu, s, o);
    if (lane == 0) {
        float z = (s + pb[0]) * 0.01f;
        out[row] = 1.0f / (1.0f + expf(-z));
    }
}

// ---------------- exact top-k via full bitonic sort (desc score, asc idx) ----
__global__ void topk_sort(const float* __restrict__ scores, int n,
                          int* __restrict__ idx_out, float* __restrict__ val_out)
{
    __shared__ unsigned long long keys[4096];
    int tid = threadIdx.x;  // 1024 threads
    for (int i = tid; i < 4096; i += 1024) {
        unsigned long long k = 0ull;
        if (i < n) {
            unsigned int fb = __float_as_uint(scores[i]);
            k = ((unsigned long long)fb << 12) | (unsigned int)(4095 - i);
        }
        keys[i] = k;
    }
    __syncthreads();
    for (int k = 2; k <= 4096; k <<= 1) {
        for (int j = k >> 1; j > 0; j >>= 1) {
            for (int t = tid; t < 4096; t += 1024) {
                int ixj = t ^ j;
                if (ixj > t) {
                    bool desc = ((t & k) == 0);
                    unsigned long long a = keys[t], b = keys[ixj];
                    if ((a < b) == desc) { keys[t] = b; keys[ixj] = a; }
                }
            }
            __syncthreads();
        }
    }
    for (int i = tid; i < 4096; i += 1024) {
        unsigned long long kk = keys[i];
        idx_out[i] = 4095 - (int)(kk & 0xFFFull);
        val_out[i] = __uint_as_float((unsigned int)(kk >> 12));
    }
}

__global__ void gather_scale(const float* __restrict__ X, const int* __restrict__ idx,
                             const float* __restrict__ vals, float* __restrict__ out, int kn)
{
    int i = blockIdx.x * 256 + threadIdx.x;
    if (i >= kn * DIM) return;
    int r = i / DIM, c = i - r * DIM;
    out[i] = X[(size_t)idx[r] * DIM + c] * vals[r];
}

__global__ void compose_idx(const int* __restrict__ a, const int* __restrict__ b,
                            int* __restrict__ out, int n)
{
    int i = blockIdx.x * 256 + threadIdx.x;
    if (i < n) out[i] = a[b[i]];
}

// -----------------------------------------------------------------------------
extern "C" void kernel_launch(void* const* d_in, const int* in_sizes, int n_in,
                              void* d_out, int out_size)
{
    const float* A       = (const float*)d_in[0];
    const float* X       = (const float*)d_in[1];
    const float* w_start = (const float*)d_in[2];  const float* b_start  = (const float*)d_in[3];
    const float* w_down0 = (const float*)d_in[4];  const float* b_down0  = (const float*)d_in[5];
    const float* w_down1 = (const float*)d_in[6];  const float* b_down1  = (const float*)d_in[7];
    const float* p_w0    = (const float*)d_in[8];  const float* p_b0     = (const float*)d_in[9];
    const float* p_w1    = (const float*)d_in[10]; const float* p_b1     = (const float*)d_in[11];
    const float* w_bottom= (const float*)d_in[12]; const float* b_bottom = (const float*)d_in[13];
    const float* w_up0   = (const float*)d_in[14]; const float* b_up0    = (const float*)d_in[15];
    const float* w_up1   = (const float*)d_in[16]; const float* b_up1    = (const float*)d_in[17];
    const float* w_end   = (const float*)d_in[18]; const float* b_end    = (const float*)d_in[19];
    float* out = (float*)d_out;

    float *AX, *AX2, *X0, *Xd0, *Xp0, *Xd1, *Xp1, *Xb, *Xu, *Xcat, *AXcat;
    float *AB1, *AB2, *ABu0, *ABu1, *sc, *v0, *v1;
    int *i0, *i1, *i01;
    cudaGetSymbolAddress((void**)&AX,    g_AX);
    cudaGetSymbolAddress((void**)&AX2,   g_AX2);
    cudaGetSymbolAddress((void**)&X0,    g_X0);
    cudaGetSymbolAddress((void**)&Xd0,   g_Xd0);
    cudaGetSymbolAddress((void**)&Xp0,   g_Xp0);
    cudaGetSymbolAddress((void**)&Xd1,   g_Xd1);
    cudaGetSymbolAddress((void**)&Xp1,   g_Xp1);
    cudaGetSymbolAddress((void**)&Xb,    g_Xb);
    cudaGetSymbolAddress((void**)&Xu,    g_Xu);
    cudaGetSymbolAddress((void**)&Xcat,  g_Xcat);
    cudaGetSymbolAddress((void**)&AXcat, g_AXcat);
    cudaGetSymbolAddress((void**)&AB1,   g_AB1);
    cudaGetSymbolAddress((void**)&AB2,   g_AB2);
    cudaGetSymbolAddress((void**)&ABu0,  g_ABu0);
    cudaGetSymbolAddress((void**)&ABu1,  g_ABu1);
    cudaGetSymbolAddress((void**)&sc,    g_scores);
    cudaGetSymbolAddress((void**)&i0,    g_idx0);
    cudaGetSymbolAddress((void**)&v0,    g_val0);
    cudaGetSymbolAddress((void**)&i1,    g_idx1);
    cudaGetSymbolAddress((void**)&v1,    g_val1);
    cudaGetSymbolAddress((void**)&i01,   g_idx01);

    auto grid = [](int M, int F) { return dim3((unsigned)(F / 64), (unsigned)((M + 63) / 64)); };
    auto eg = [](int n) { return (unsigned)((n * DIM + 255) / 256); };

    // ---- start: X0 = relu((A@X)@w_start + b); also -> out_start, Xcat right
    gemm_f2<<<grid(NN, DIM), 128>>>(A, NN, X, DIM, AX, DIM, NN, NN);
    gemm_f2<<<grid(NN, DIM), 128>>>(AX, DIM, w_start, DIM, AX2, DIM, NN, DIM);
    epilogue<<<eg(NN), 256>>>(AX2, b_start, nullptr, X0, DIM, Xcat + DIM, 2 * DIM, NN);
    cudaMemcpyAsync(out + OFF_START, X0, (size_t)NN * DIM * sizeof(float),
                    cudaMemcpyDeviceToDevice, 0);

    // ---- Xd0 = gcn(A, X0, w_down0); A@X0 saved as right half of AXcat (reused at end)
    gemm_f2<<<grid(NN, DIM), 128>>>(A, NN, X0, DIM, AXcat + DIM, 2 * DIM, NN, NN);
    gemm_f2<<<grid(NN, DIM), 128>>>(AXcat + DIM, 2 * DIM, w_down0, DIM, AX2, DIM, NN, DIM);
    epilogue<<<eg(NN), 256>>>(AX2, b_down0, nullptr, Xd0, DIM, nullptr, 0, NN);

    // ---- pool 0
    scores_kernel<<<(NN + 7) / 8, 256>>>(Xd0, NN, p_w0, p_b0, sc);
    topk_sort<<<1, 1024>>>(sc, NN, i0, v0);
    gather_scale<<<(KP0 * DIM + 255) / 256, 256>>>(Xd0, i0, v0, Xp0, KP0);
    gatherA<<<dim3((KP0P + 255) / 256, KP0), 256>>>(AB1, KP0P, A, i0, i0, KP0, KP0, KP0P);
    gatherA<<<dim3((KP0P + 255) / 256, NN), 256>>>(ABu1, KP0P, A, nullptr, i0, NN, KP0, KP0P);

    // ---- Xd1 = gcn(A1, Xp0, w_down1)
    gemm_f2<<<grid(KP0, DIM), 128>>>(AB1, KP0P, Xp0, DIM, AX, DIM, KP0, KP0P);
    gemm_f2<<<grid(KP0, DIM), 128>>>(AX, DIM, w_down1, DIM, AX2, DIM, KP0, DIM);
    epilogue<<<eg(KP0), 256>>>(AX2, b_down1, nullptr, Xd1, DIM, nullptr, 0, KP0);

    // ---- pool 1
    scores_kernel<<<(KP0 + 7) / 8, 256>>>(Xd1, KP0, p_w1, p_b1, sc);
    topk_sort<<<1, 1024>>>(sc, KP0, i1, v1);
    gather_scale<<<(KP1 * DIM + 255) / 256, 256>>>(Xd1, i1, v1, Xp1, KP1);
    compose_idx<<<(KP1 + 255) / 256, 256>>>(i0, i1, i01, KP1);
    gatherA<<<dim3((KP1P + 255) / 256, KP1), 256>>>(AB2, KP1P, A, i01, i01, KP1, KP1, KP1P);
    gatherA<<<dim3((KP1P + 255) / 256, KP0), 256>>>(ABu0, KP1P, A, i0, i01, KP0, KP1, KP1P);

    // ---- bottom: Xb = gcn(A2, Xp1, w_bottom)
    gemm_f2<<<grid(KP1, DIM), 128>>>(AB2, KP1P, Xp1, DIM, AX, DIM, KP1, KP1P);
    gemm_f2<<<grid(KP1, DIM), 128>>>(AX, DIM, w_bottom, DIM, AX2, DIM, KP1, DIM);
    epilogue<<<eg(KP1), 256>>>(AX2, b_bottom, nullptr, Xb, DIM, nullptr, 0, KP1);

    // ---- up 0: Xu = gcn(A1, scatter(Xb), w_up0) + Xd1  (scatter folded into gather)
    gemm_f2<<<grid(KP0, DIM), 128>>>(ABu0, KP1P, Xb, DIM, AX, DIM, KP0, KP1P);
    gemm_f2<<<grid(KP0, DIM), 128>>>(AX, DIM, w_up0, DIM, AX2, DIM, KP0, DIM);
    epilogue<<<eg(KP0), 256>>>(AX2, b_up0, Xd1, Xu, DIM, nullptr, 0, KP0);

    // ---- up 1: Xu2 = gcn(A, scatter(Xu), w_up1) + Xd0 -> Xcat left half
    gemm_f2<<<grid(NN, DIM), 128>>>(ABu1, KP0P, Xu, DIM, AX, DIM, NN, KP0P);
    gemm_f2<<<grid(NN, DIM), 128>>>(AX, DIM, w_up1, DIM, AX2, DIM, NN, DIM);
    epilogue<<<eg(NN), 256>>>(AX2, b_up1, Xd0, Xcat, 2 * DIM, nullptr, 0, NN);

    // ---- end: Xout = gcn(A, Xcat, w_end); right half of A@Xcat reused from Xd0 stage
    gemm_f2<<<grid(NN, DIM), 128>>>(A, NN, Xcat, 2 * DIM, AXcat, 2 * DIM, NN, NN);
    gemm_f2<<<grid(NN, DIM), 128>>>(AXcat, 2 * DIM, w_end, DIM, AX2, DIM, NN, 2 * DIM);
    epilogue<<<eg(NN), 256>>>(AX2, b_end, nullptr, out, DIM, nullptr, 0, NN);

    // ---- pool_out = Xp0 @ Xp0^T (triangular + mirror), diag = 1
    pool_gemm<<<dim3((KP0 + 63) / 64, (KP0 + 63) / 64), 128>>>(Xp0, out + OFF_POOL, KP0);
}

// round 3
// speedup vs baseline: 1.0997x; 1.0560x over previous
#include <cuda_runtime.h>

#define NN   4096
#define DIM  320
#define KP0  3686
#define KP1  2580
#define KP0P 3696   // KP0 padded to multiple of 16
#define KP1P 2592   // KP1 padded to multiple of 16

#define OFF_START (NN*DIM)
#define OFF_POOL  (2*NN*DIM)

// ---------------- scratch (static device globals; no allocation) -------------
// zero-initialized at module load; padded rows/cols are never written -> stay 0
__device__ __align__(16) float g_P    [2*NN*DIM];     // adjacency-GEMM k-slices
__device__ __align__(16) float g_Q    [2*NN*DIM];     // feature-GEMM k-slices
__device__ __align__(16) float g_AXp  [2*NN*2*DIM];   // A@[Xu2|X0] k-slices (cat trick)
__device__ __align__(16) float g_X0   [NN*DIM];
__device__ __align__(16) float g_Xd0  [NN*DIM];
__device__ __align__(16) float g_Xp0  [KP0P*DIM];
__device__ __align__(16) float g_Xd1  [KP0*DIM];
__device__ __align__(16) float g_Xp1  [KP1P*DIM];
__device__ __align__(16) float g_Xb   [KP1P*DIM];
__device__ __align__(16) float g_Xu   [KP0P*DIM];
__device__ __align__(16) float g_Xcat [NN*2*DIM];
__device__ __align__(16) float g_AB1  [(size_t)KP0*KP0P];
__device__ __align__(16) float g_AB2  [(size_t)KP1*KP1P];
__device__ __align__(16) float g_ABu0 [(size_t)KP0*KP1P];
__device__ __align__(16) float g_ABu1 [(size_t)NN*KP0P];
__device__ float g_scores[NN];
__device__ int   g_idx0[NN];
__device__ float g_val0[NN];
__device__ int   g_idx1[NN];
__device__ float g_val1[NN];
__device__ int   g_idx01[KP1];

typedef unsigned long long u64;

__device__ __forceinline__ void ffma2(u64& c, u64 a, u64 b) {
    asm("fma.rn.f32x2 %0, %1, %2, %0;" : "+l"(c) : "l"(a), "l"(b));
}
__device__ __forceinline__ u64 dup2(float x) {
    u64 r;
    asm("mov.b64 %0, {%1, %1};" : "=l"(r) : "f"(x));
    return r;
}

// ---------------- SGEMM, 256 thr, 64x64x16, 4x4/thread, f32x2, split-K -------
// C_z = (A+A2)[:, kslice_z] @ (B+B2)[kslice_z, :]    z = blockIdx.z in {0,1}
// kslice_0 = [0,kSplit), kslice_1 = [kSplit,kTotal); each a multiple of 16.
// A2/B2 optional (element-wise added on load). C slice offset = z*partStride.
__global__ void __launch_bounds__(256, 5)
gemm256(const float* __restrict__ A, const float* __restrict__ A2, int lda,
        const float* __restrict__ B, const float* __restrict__ B2, int ldb,
        float* __restrict__ C, int ldc, long long partStride,
        int M, int kSplit, int kTotal)
{
    __shared__ u64   As2[2][16][64];
    __shared__ float Bs [2][16][64];

    int tid = threadIdx.x;
    int tx = tid & 15, ty = tid >> 4;
    int bm0 = blockIdx.y * 64, bn0 = blockIdx.x * 64;
    int kb = blockIdx.z ? kSplit : 0;
    int ke = blockIdx.z ? kTotal : kSplit;
    C += (long long)blockIdx.z * partStride;

    // A loader: 4 consecutive k per thread
    int a_r = tid >> 2, a_k = (tid & 3) * 4;
    int a_gm = bm0 + a_r;
    const float* Arow  = (a_gm < M) ? A + (size_t)a_gm * lda + kb + a_k : nullptr;
    const float* Arow2 = (A2 && a_gm < M) ? A2 + (size_t)a_gm * lda + kb + a_k : nullptr;

    // B loader: 4 consecutive cols per thread
    int b_k = tid >> 4, b_n = (tid & 15) * 4;
    const float* Bb  = B + (size_t)(kb + b_k) * ldb + bn0 + b_n;
    const float* Bb2 = B2 ? B2 + (size_t)(kb + b_k) * ldb + bn0 + b_n : nullptr;

    int T = (ke - kb) >> 4;

    u64 acc[4][2];
#pragma unroll
    for (int i = 0; i < 4; i++) { acc[i][0] = 0ull; acc[i][1] = 0ull; }

    float4 ra, rb;
    auto loadT = [&](int t) {
        if (Arow) {
            ra = *reinterpret_cast<const float4*>(Arow + t * 16);
            if (Arow2) {
                float4 c = *reinterpret_cast<const float4*>(Arow2 + t * 16);
                ra.x += c.x; ra.y += c.y; ra.z += c.z; ra.w += c.w;
            }
        } else ra = make_float4(0.f, 0.f, 0.f, 0.f);
        rb = *reinterpret_cast<const float4*>(Bb + (size_t)t * 16 * ldb);
        if (Bb2) {
            float4 c = *reinterpret_cast<const float4*>(Bb2 + (size_t)t * 16 * ldb);
            rb.x += c.x; rb.y += c.y; rb.z += c.z; rb.w += c.w;
        }
    };
    auto stage = [&](int buf) {
        As2[buf][a_k + 0][a_r] = dup2(ra.x);
        As2[buf][a_k + 1][a_r] = dup2(ra.y);
        As2[buf][a_k + 2][a_r] = dup2(ra.z);
        As2[buf][a_k + 3][a_r] = dup2(ra.w);
        *reinterpret_cast<float4*>(&Bs[buf][b_k][b_n]) = rb;
    };

    loadT(0);
    stage(0);
    __syncthreads();
    if (T > 1) loadT(1);

    for (int t = 0; t < T; t++) {
        int buf = t & 1;
#pragma unroll
        for (int kk = 0; kk < 16; kk++) {
            ulonglong2 b2 = *reinterpret_cast<const ulonglong2*>(&Bs[buf][kk][tx * 4]);
            ulonglong2 aa = *reinterpret_cast<const ulonglong2*>(&As2[buf][kk][ty * 4 + 0]);
            ulonglong2 ab = *reinterpret_cast<const ulonglong2*>(&As2[buf][kk][ty * 4 + 2]);
            ffma2(acc[0][0], aa.x, b2.x); ffma2(acc[0][1], aa.x, b2.y);
            ffma2(acc[1][0], aa.y, b2.x); ffma2(acc[1][1], aa.y, b2.y);
            ffma2(acc[2][0], ab.x, b2.x); ffma2(acc[2][1], ab.x, b2.y);
            ffma2(acc[3][0], ab.y, b2.x); ffma2(acc[3][1], ab.y, b2.y);
        }
        if (t + 1 < T) {
            stage(buf ^ 1);            // regs hold tile t+1
            __syncthreads();
            if (t + 2 < T) loadT(t + 2);
        }
    }

#pragma unroll
    for (int i = 0; i < 4; i++) {
        int m = bm0 + ty * 4 + i;
        if (m < M) {
            ulonglong2 v; v.x = acc[i][0]; v.y = acc[i][1];
            *reinterpret_cast<ulonglong2*>(C + (size_t)m * ldc + bn0 + tx * 4) = v;
        }
    }
}

// ---------------- pool_out = X @ X^T (triangular, mirrored), diag = 1 --------
__global__ void __launch_bounds__(256, 5)
pool_gemm(const float* __restrict__ X, float* __restrict__ out, int n)
{
    int bm0 = blockIdx.y * 64, bn0 = blockIdx.x * 64;
    if (bn0 < bm0) return;   // triangular

    __shared__ u64   As2[16][64];
    __shared__ float Bs [16][64];

    int tid = threadIdx.x;
    int tx = tid & 15, ty = tid >> 4;
    int l_r = tid >> 2, l_k = (tid & 3) * 4;
    int a_gm = bm0 + l_r;
    int b_gn = bn0 + l_r;
    const float* Arow = (a_gm < n) ? X + (size_t)a_gm * DIM + l_k : nullptr;
    const float* Brow = (b_gn < n) ? X + (size_t)b_gn * DIM + l_k : nullptr;

    u64 acc[4][2];
#pragma unroll
    for (int i = 0; i < 4; i++) { acc[i][0] = 0ull; acc[i][1] = 0ull; }

    for (int k0 = 0; k0 < DIM; k0 += 16) {
        float4 va = Arow ? *reinterpret_cast<const float4*>(Arow + k0) : make_float4(0,0,0,0);
        float4 vb = Brow ? *reinterpret_cast<const float4*>(Brow + k0) : make_float4(0,0,0,0);
        As2[l_k + 0][l_r] = dup2(va.x); As2[l_k + 1][l_r] = dup2(va.y);
        As2[l_k + 2][l_r] = dup2(va.z); As2[l_k + 3][l_r] = dup2(va.w);
        Bs[l_k + 0][l_r] = vb.x; Bs[l_k + 1][l_r] = vb.y;
        Bs[l_k + 2][l_r] = vb.z; Bs[l_k + 3][l_r] = vb.w;
        __syncthreads();
#pragma unroll
        for (int kk = 0; kk < 16; kk++) {
            ulonglong2 b2 = *reinterpret_cast<const ulonglong2*>(&Bs[kk][tx * 4]);
            ulonglong2 aa = *reinterpret_cast<const ulonglong2*>(&As2[kk][ty * 4 + 0]);
            ulonglong2 ab = *reinterpret_cast<const ulonglong2*>(&As2[kk][ty * 4 + 2]);
            ffma2(acc[0][0], aa.x, b2.x); ffma2(acc[0][1], aa.x, b2.y);
            ffma2(acc[1][0], aa.y, b2.x); ffma2(acc[1][1], aa.y, b2.y);
            ffma2(acc[2][0], ab.x, b2.x); ffma2(acc[2][1], ab.x, b2.y);
            ffma2(acc[3][0], ab.y, b2.x); ffma2(acc[3][1], ab.y, b2.y);
        }
        __syncthreads();
    }

#pragma unroll
    for (int i = 0; i < 4; i++) {
        int gi = bm0 + ty * 4 + i;
        if (gi >= n) continue;
        float f[4];
        *reinterpret_cast<ulonglong2*>(f) = *reinterpret_cast<ulonglong2*>(&acc[i][0]);
#pragma unroll
        for (int j = 0; j < 4; j++) {
            int gj = bn0 + tx * 4 + j;
            if (gj < n) {
                float v = (gi == gj) ? 1.0f : f[j];
                out[(size_t)gi * n + gj] = v;
                out[(size_t)gj * n + gi] = v;
            }
        }
    }
}

// ---------------- gather materialization of sub-adjacency --------------------
__global__ void gatherA(float* __restrict__ dst, int ldd,
                        const float* __restrict__ A,
                        const int* __restrict__ ridx, const int* __restrict__ cidx,
                        int M, int Ksub, int Kpad)
{
    int k = blockIdx.x * 256 + threadIdx.x;
    int m = blockIdx.y;
    if (k >= Kpad || m >= M) return;
    float v = 0.f;
    if (k < Ksub) {
        int r = ridx ? ridx[m] : m;
        v = __ldg(&A[(size_t)r * NN + cidx[k]]);
    }
    dst[(size_t)m * ldd + k] = v;
}

// ---------------- bias + ReLU (+residual), two k-slice inputs ----------------
__global__ void epilogue(const float* __restrict__ T, const float* __restrict__ T2,
                         const float* __restrict__ bias, const float* __restrict__ R,
                         float* __restrict__ d1, int ld1,
                         float* __restrict__ d2, int ld2, int n)
{
    int i = blockIdx.x * blockDim.x + threadIdx.x;
    if (i >= n * DIM) return;
    int r = i / DIM, c = i - r * DIM;
    float v = T[i] + (T2 ? T2[i] : 0.f) + bias[c];
    v = v > 0.f ? v : 0.f;
    if (R) v += R[i];
    d1[(size_t)r * ld1 + c] = v;
    if (d2) d2[(size_t)r * ld2 + c] = v;
}

// ---------------- pooling scores: sigmoid((X . pw + pb)/100) -----------------
__global__ void scores_kernel(const float* __restrict__ X, int n,
                              const float* __restrict__ pw, const float* __restrict__ pb,
                              float* __restrict__ out)
{
    int row = blockIdx.x * 8 + (threadIdx.x >> 5);
    int lane = threadIdx.x & 31;
    if (row >= n) return;
    float s = 0.f;
    for (int c = lane; c < DIM; c += 32) s += X[(size_t)row * DIM + c] * pw[c];
#pragma unroll
    for (int o = 16; o > 0; o >>= 1) s += __shfl_down_sync(0xffffffffu, s, o);
    if (lane == 0) {
        float z = (s + pb[0]) * 0.01f;
        out[row] = 1.0f / (1.0f + expf(-z));
    }
}

// ---------------- exact top-k via full bitonic sort (desc score, asc idx) ----
__global__ void topk_sort(const float* __restrict__ scores, int n,
                          int* __restrict__ idx_out, float* __restrict__ val_out)
{
    __shared__ unsigned long long keys[4096];
    int tid = threadIdx.x;  // 1024 threads
    for (int i = tid; i < 4096; i += 1024) {
        unsigned long long k = 0ull;
        if (i < n) {
            unsigned int fb = __float_as_uint(scores[i]);
            k = ((unsigned long long)fb << 12) | (unsigned int)(4095 - i);
        }
        keys[i] = k;
    }
    __syncthreads();
    for (int k = 2; k <= 4096; k <<= 1) {
        for (int j = k >> 1; j > 0; j >>= 1) {
            for (int t = tid; t < 4096; t += 1024) {
                int ixj = t ^ j;
                if (ixj > t) {
                    bool desc = ((t & k) == 0);
                    unsigned long long a = keys[t], b = keys[ixj];
                    if ((a < b) == desc) { keys[t] = b; keys[ixj] = a; }
                }
            }
            __syncthreads();
        }
    }
    for (int i = tid; i < 4096; i += 1024) {
        unsigned long long kk = keys[i];
        idx_out[i] = 4095 - (int)(kk & 0xFFFull);
        val_out[i] = __uint_as_float((unsigned int)(kk >> 12));
    }
}

__global__ void gather_scale(const float* __restrict__ X, const int* __restrict__ idx,
                             const float* __restrict__ vals, float* __restrict__ out, int kn)
{
    int i = blockIdx.x * 256 + threadIdx.x;
    if (i >= kn * DIM) return;
    int r = i / DIM, c = i - r * DIM;
    out[i] = X[(size_t)idx[r] * DIM + c] * vals[r];
}

__global__ void compose_idx(const int* __restrict__ a, const int* __restrict__ b,
                            int* __restrict__ out, int n)
{
    int i = blockIdx.x * 256 + threadIdx.x;
    if (i < n) out[i] = a[b[i]];
}

// -----------------------------------------------------------------------------
extern "C" void kernel_launch(void* const* d_in, const int* in_sizes, int n_in,
                              void* d_out, int out_size)
{
    const float* A       = (const float*)d_in[0];
    const float* X       = (const float*)d_in[1];
    const float* w_start = (const float*)d_in[2];  const float* b_start  = (const float*)d_in[3];
    const float* w_down0 = (const float*)d_in[4];  const float* b_down0  = (const float*)d_in[5];
    const float* w_down1 = (const float*)d_in[6];  const float* b_down1  = (const float*)d_in[7];
    const float* p_w0    = (const float*)d_in[8];  const float* p_b0     = (const float*)d_in[9];
    const float* p_w1    = (const float*)d_in[10]; const float* p_b1     = (const float*)d_in[11];
    const float* w_bottom= (const float*)d_in[12]; const float* b_bottom = (const float*)d_in[13];
    const float* w_up0   = (const float*)d_in[14]; const float* b_up0    = (const float*)d_in[15];
    const float* w_up1   = (const float*)d_in[16]; const float* b_up1    = (const float*)d_in[17];
    const float* w_end   = (const float*)d_in[18]; const float* b_end    = (const float*)d_in[19];
    float* out = (float*)d_out;

    float *P, *Q, *AXp, *X0, *Xd0, *Xp0, *Xd1, *Xp1, *Xb, *Xu, *Xcat;
    float *AB1, *AB2, *ABu0, *ABu1, *sc, *v0, *v1;
    int *i0, *i1, *i01;
    cudaGetSymbolAddress((void**)&P,    g_P);
    cudaGetSymbolAddress((void**)&Q,    g_Q);
    cudaGetSymbolAddress((void**)&AXp,  g_AXp);
    cudaGetSymbolAddress((void**)&X0,   g_X0);
    cudaGetSymbolAddress((void**)&Xd0,  g_Xd0);
    cudaGetSymbolAddress((void**)&Xp0,  g_Xp0);
    cudaGetSymbolAddress((void**)&Xd1,  g_Xd1);
    cudaGetSymbolAddress((void**)&Xp1,  g_Xp1);
    cudaGetSymbolAddress((void**)&Xb,   g_Xb);
    cudaGetSymbolAddress((void**)&Xu,   g_Xu);
    cudaGetSymbolAddress((void**)&Xcat, g_Xcat);
    cudaGetSymbolAddress((void**)&AB1,  g_AB1);
    cudaGetSymbolAddress((void**)&AB2,  g_AB2);
    cudaGetSymbolAddress((void**)&ABu0, g_ABu0);
    cudaGetSymbolAddress((void**)&ABu1, g_ABu1);
    cudaGetSymbolAddress((void**)&sc,   g_scores);
    cudaGetSymbolAddress((void**)&i0,   g_idx0);
    cudaGetSymbolAddress((void**)&v0,   g_val0);
    cudaGetSymbolAddress((void**)&i1,   g_idx1);
    cudaGetSymbolAddress((void**)&v1,   g_val1);
    cudaGetSymbolAddress((void**)&i01,  g_idx01);

    const long long PS  = (long long)NN * DIM;       // P/Q slice stride
    const long long PSX = (long long)NN * 2 * DIM;   // AXp slice stride
    float* P1 = P + PS;
    float* Q1 = Q + PS;
    float* AXp1 = AXp + PSX;

    auto launchG = [](const float* A_, const float* A2_, int lda_,
                      const float* B_, const float* B2_, int ldb_,
                      float* C_, int ldc_, long long pstride_,
                      int M_, int N_, int K_) {
        int kSplit = (K_ / 2) & ~15;
        dim3 g((unsigned)(N_ / 64), (unsigned)((M_ + 63) / 64), 2);
        gemm256<<<g, 256>>>(A_, A2_, lda_, B_, B2_, ldb_, C_, ldc_, pstride_, M_, kSplit, K_);
    };
    auto eg = [](int n) { return (unsigned)((n * DIM + 255) / 256); };

    // ---- start: X0 = relu((A@X)@w_start + b); -> out_start, Xcat right half
    launchG(A, nullptr, NN, X, nullptr, DIM, P, DIM, PS, NN, DIM, NN);
    launchG(P, P1, DIM, w_start, nullptr, DIM, Q, DIM, PS, NN, DIM, DIM);
    epilogue<<<eg(NN), 256>>>(Q, Q1, b_start, nullptr, X0, DIM, Xcat + DIM, 2 * DIM, NN);
    cudaMemcpyAsync(out + OFF_START, X0, (size_t)NN * DIM * sizeof(float),
                    cudaMemcpyDeviceToDevice, 0);

    // ---- Xd0 = gcn(A, X0, w_down0); A@X0 slices kept in AXp right half (end reuse)
    launchG(A, nullptr, NN, X0, nullptr, DIM, AXp + DIM, 2 * DIM, PSX, NN, DIM, NN);
    launchG(AXp + DIM, AXp1 + DIM, 2 * DIM, w_down0, nullptr, DIM, Q, DIM, PS, NN, DIM, DIM);
    epilogue<<<eg(NN), 256>>>(Q, Q1, b_down0, nullptr, Xd0, DIM, nullptr, 0, NN);

    // ---- pool 0
    scores_kernel<<<(NN + 7) / 8, 256>>>(Xd0, NN, p_w0, p_b0, sc);
    topk_sort<<<1, 1024>>>(sc, NN, i0, v0);
    gather_scale<<<(KP0 * DIM + 255) / 256, 256>>>(Xd0, i0, v0, Xp0, KP0);
    gatherA<<<dim3((KP0P + 255) / 256, KP0), 256>>>(AB1, KP0P, A, i0, i0, KP0, KP0, KP0P);
    gatherA<<<dim3((KP0P + 255) / 256, NN), 256>>>(ABu1, KP0P, A, nullptr, i0, NN, KP0, KP0P);

    // ---- Xd1 = gcn(A1, Xp0, w_down1)
    launchG(AB1, nullptr, KP0P, Xp0, nullptr, DIM, P, DIM, PS, KP0, DIM, KP0P);
    launchG(P, P1, DIM, w_down1, nullptr, DIM, Q, DIM, PS, KP0, DIM, DIM);
    epilogue<<<eg(KP0), 256>>>(Q, Q1, b_down1, nullptr, Xd1, DIM, nullptr, 0, KP0);

    // ---- pool 1
    scores_kernel<<<(KP0 + 7) / 8, 256>>>(Xd1, KP0, p_w1, p_b1, sc);
    topk_sort<<<1, 1024>>>(sc, KP0, i1, v1);
    gather_scale<<<(KP1 * DIM + 255) / 256, 256>>>(Xd1, i1, v1, Xp1, KP1);
    compose_idx<<<(KP1 + 255) / 256, 256>>>(i0, i1, i01, KP1);
    gatherA<<<dim3((KP1P + 255) / 256, KP1), 256>>>(AB2, KP1P, A, i01, i01, KP1, KP1, KP1P);
    gatherA<<<dim3((KP1P + 255) / 256, KP0), 256>>>(ABu0, KP1P, A, i0, i01, KP0, KP1, KP1P);

    // ---- bottom: Xb = gcn(A2, Xp1, w_bottom)
    launchG(AB2, nullptr, KP1P, Xp1, nullptr, DIM, P, DIM, PS, KP1, DIM, KP1P);
    launchG(P, P1, DIM, w_bottom, nullptr, DIM, Q, DIM, PS, KP1, DIM, DIM);
    epilogue<<<eg(KP1), 256>>>(Q, Q1, b_bottom, nullptr, Xb, DIM, nullptr, 0, KP1);

    // ---- up 0: Xu = gcn(A1, scatter(Xb), w_up0) + Xd1  (scatter folded into gather)
    launchG(ABu0, nullptr, KP1P, Xb, nullptr, DIM, P, DIM, PS, KP0, DIM, KP1P);
    launchG(P, P1, DIM, w_up0, nullptr, DIM, Q, DIM, PS, KP0, DIM, DIM);
    epilogue<<<eg(KP0), 256>>>(Q, Q1, b_up0, Xd1, Xu, DIM, nullptr, 0, KP0);

    // ---- up 1: Xu2 = gcn(A, scatter(Xu), w_up1) + Xd0 -> Xcat left half
    launchG(ABu1, nullptr, KP0P, Xu, nullptr, DIM, P, DIM, PS, NN, DIM, KP0P);
    launchG(P, P1, DIM, w_up1, nullptr, DIM, Q, DIM, PS, NN, DIM, DIM);
    epilogue<<<eg(NN), 256>>>(Q, Q1, b_up1, Xd0, Xcat, 2 * DIM, nullptr, 0, NN);

    // ---- end: Xout = gcn(A, Xcat, w_end); right half of A@Xcat reused from Xd0 stage
    launchG(A, nullptr, NN, Xcat, nullptr, 2 * DIM, AXp, 2 * DIM, PSX, NN, DIM, NN);
    launchG(AXp, AXp1, 2 * DIM, w_end, nullptr, DIM, Q, DIM, PS, NN, DIM, 2 * DIM);
    epilogue<<<eg(NN), 256>>>(Q, Q1, b_end, nullptr, out, DIM, nullptr, 0, NN);

    // ---- pool_out = Xp0 @ Xp0^T (triangular + mirror), diag = 1
    pool_gemm<<<dim3((KP0 + 63) / 64, (KP0 + 63) / 64), 256>>>(Xp0, out + OFF_POOL, KP0);
}

// round 4
// speedup vs baseline: 1.4337x; 1.3037x over previous
#include <cuda_runtime.h>

#define NN   4096
#define DIM  320
#define KP0  3686
#define KP1  2580
#define KP0P 3696   // KP0 padded to multiple of 16
#define KP1P 2592   // KP1 padded to multiple of 16

#define OFF_START (NN*DIM)
#define OFF_POOL  (2*NN*DIM)

// ---------------- scratch (static device globals; no allocation) -------------
// zero-initialized at load; padded rows are never written -> stay 0
__device__ __align__(16) float g_P    [4*NN*DIM];     // adjacency-GEMM k-slices
__device__ __align__(16) float g_Q    [4*NN*DIM];     // feature-GEMM k-slices
__device__ __align__(16) float g_AXp  [4*NN*2*DIM];   // A@[Xu2|X0] k-slices
__device__ __align__(16) float g_X0   [NN*DIM];
__device__ __align__(16) float g_Xd0  [NN*DIM];
__device__ __align__(16) float g_Xp0  [KP0P*DIM];
__device__ __align__(16) float g_Xd1  [KP0*DIM];
__device__ __align__(16) float g_Xp1  [KP1P*DIM];
__device__ __align__(16) float g_Xb   [KP1P*DIM];
__device__ __align__(16) float g_Xu   [KP0P*DIM];
__device__ __align__(16) float g_Xcat [NN*2*DIM];
__device__ __align__(16) float g_AB1  [(size_t)KP0*KP0P];
__device__ __align__(16) float g_AB2  [(size_t)KP1*KP1P];
__device__ __align__(16) float g_ABu0 [(size_t)KP0*KP1P];
__device__ __align__(16) float g_ABu1 [(size_t)NN*KP0P];
__device__ float g_scores[NN];
__device__ int   g_idx0[NN];
__device__ float g_val0[NN];
__device__ int   g_idx1[NN];
__device__ float g_val1[NN];
__device__ int   g_idx01[KP1];

typedef unsigned long long u64;

__device__ __forceinline__ void ffma2(u64& c, u64 a, u64 b) {
    asm("fma.rn.f32x2 %0, %1, %2, %0;" : "+l"(c) : "l"(a), "l"(b));
}
__device__ __forceinline__ u64 dup2(float x) {
    u64 r;
    asm("mov.b64 %0, {%1, %1};" : "=l"(r) : "f"(x));
    return r;
}

// ---------------- SGEMM 128x64x16, 128 thr, 8x8/thread, f32x2, split-K=4 -----
// C_z = (sum_s A_s)[:, kslice_z] @ B[kslice_z, :]
// A_s = A + s*sliceA for s in [0, nSl). kslice_z = [z*kChunk, min(+kChunk,K)).
// C slice offset = z*partStride. K and kChunk multiples of 16. N mult of 64.
__global__ void __launch_bounds__(128, 4)
gemmBig(const float* __restrict__ A, long long sliceA, int nSl, int lda,
        const float* __restrict__ B, int ldb,
        float* __restrict__ C, int ldc, long long partStride,
        int M, int kChunk, int K)
{
    __shared__ float As[2][16][128];
    __shared__ float Bs[2][16][64];

    int tid = threadIdx.x;
    int tx = tid & 7, ty = tid >> 3;             // compute map: 8 cols x 8 rows blocks
    int bm0 = blockIdx.y * 128, bn0 = blockIdx.x * 64;
    int kb = blockIdx.z * kChunk;
    int ke = kb + kChunk; if (ke > K) ke = K;
    int T = (ke - kb) >> 4;
    C += (long long)blockIdx.z * partStride;

    // A loader: 32 rows x 16 k per pass, 4 passes (rows += 32)
    int a_r = tid >> 2, a_k = (tid & 3) * 4;
    // B loader: 8 k-rows x 64 cols per pass, 2 passes (k += 8)
    int b_r = tid >> 4, b_c = (tid & 15) * 4;

    u64 acc[8][4];
#pragma unroll
    for (int i = 0; i < 8; i++)
#pragma unroll
        for (int j = 0; j < 4; j++) acc[i][j] = 0ull;

    float4 ra[4], rb[2];

    auto loadT = [&](int t) {
        long long kOff = (long long)kb + t * 16;
#pragma unroll
        for (int p = 0; p < 4; p++) {
            int gm = bm0 + a_r + 32 * p;
            float4 v = make_float4(0.f, 0.f, 0.f, 0.f);
            if (gm < M) {
                const float* ptr = A + (size_t)gm * lda + kOff + a_k;
                v = *reinterpret_cast<const float4*>(ptr);
                for (int s = 1; s < nSl; s++) {
                    float4 w = *reinterpret_cast<const float4*>(ptr + (size_t)s * sliceA);
                    v.x += w.x; v.y += w.y; v.z += w.z; v.w += w.w;
                }
            }
            ra[p] = v;
        }
#pragma unroll
        for (int p = 0; p < 2; p++)
            rb[p] = *reinterpret_cast<const float4*>(
                B + (size_t)(kOff + b_r + 8 * p) * ldb + bn0 + b_c);
    };
    auto stage = [&](int buf) {
#pragma unroll
        for (int p = 0; p < 4; p++) {
            int r = a_r + 32 * p;
            As[buf][a_k + 0][r] = ra[p].x;
            As[buf][a_k + 1][r] = ra[p].y;
            As[buf][a_k + 2][r] = ra[p].z;
            As[buf][a_k + 3][r] = ra[p].w;
        }
#pragma unroll
        for (int p = 0; p < 2; p++)
            *reinterpret_cast<float4*>(&Bs[buf][b_r + 8 * p][b_c]) = rb[p];
    };

    if (T > 0) {
        loadT(0);
        stage(0);
        __syncthreads();
        if (T > 1) loadT(1);
    }

    for (int t = 0; t < T; t++) {
        int buf = t & 1;
#pragma unroll
        for (int kk = 0; kk < 16; kk++) {
            ulonglong2 b01 = *reinterpret_cast<const ulonglong2*>(&Bs[buf][kk][tx * 8]);
            ulonglong2 b23 = *reinterpret_cast<const ulonglong2*>(&Bs[buf][kk][tx * 8 + 4]);
            float4 a03 = *reinterpret_cast<const float4*>(&As[buf][kk][ty * 8]);
            float4 a47 = *reinterpret_cast<const float4*>(&As[buf][kk][ty * 8 + 4]);
            u64 ad0 = dup2(a03.x), ad1 = dup2(a03.y), ad2 = dup2(a03.z), ad3 = dup2(a03.w);
            u64 ad4 = dup2(a47.x), ad5 = dup2(a47.y), ad6 = dup2(a47.z), ad7 = dup2(a47.w);
            ffma2(acc[0][0], ad0, b01.x); ffma2(acc[0][1], ad0, b01.y);
            ffma2(acc[0][2], ad0, b23.x); ffma2(acc[0][3], ad0, b23.y);
            ffma2(acc[1][0], ad1, b01.x); ffma2(acc[1][1], ad1, b01.y);
            ffma2(acc[1][2], ad1, b23.x); ffma2(acc[1][3], ad1, b23.y);
            ffma2(acc[2][0], ad2, b01.x); ffma2(acc[2][1], ad2, b01.y);
            ffma2(acc[2][2], ad2, b23.x); ffma2(acc[2][3], ad2, b23.y);
            ffma2(acc[3][0], ad3, b01.x); ffma2(acc[3][1], ad3, b01.y);
            ffma2(acc[3][2], ad3, b23.x); ffma2(acc[3][3], ad3, b23.y);
            ffma2(acc[4][0], ad4, b01.x); ffma2(acc[4][1], ad4, b01.y);
            ffma2(acc[4][2], ad4, b23.x); ffma2(acc[4][3], ad4, b23.y);
            ffma2(acc[5][0], ad5, b01.x); ffma2(acc[5][1], ad5, b01.y);
            ffma2(acc[5][2], ad5, b23.x); ffma2(acc[5][3], ad5, b23.y);
            ffma2(acc[6][0], ad6, b01.x); ffma2(acc[6][1], ad6, b01.y);
            ffma2(acc[6][2], ad6, b23.x); ffma2(acc[6][3], ad6, b23.y);
            ffma2(acc[7][0], ad7, b01.x); ffma2(acc[7][1], ad7, b01.y);
            ffma2(acc[7][2], ad7, b23.x); ffma2(acc[7][3], ad7, b23.y);
        }
        if (t + 1 < T) {
            stage(buf ^ 1);        // regs hold tile t+1
            __syncthreads();
            if (t + 2 < T) loadT(t + 2);
        }
    }

#pragma unroll
    for (int i = 0; i < 8; i++) {
        int m = bm0 + ty * 8 + i;
        if (m < M) {
            float* cp = C + (size_t)m * ldc + bn0 + tx * 8;
            ulonglong2 v0; v0.x = acc[i][0]; v0.y = acc[i][1];
            ulonglong2 v1; v1.x = acc[i][2]; v1.y = acc[i][3];
            *reinterpret_cast<ulonglong2*>(cp) = v0;
            *reinterpret_cast<ulonglong2*>(cp + 4) = v1;
        }
    }
}

// ---------------- pool_out = X @ X^T (triangular, mirrored), diag = 1 --------
__global__ void __launch_bounds__(128, 4)
pool_gemm(const float* __restrict__ X, float* __restrict__ out, int n)
{
    int bm0 = blockIdx.y * 128, bn0 = blockIdx.x * 64;
    if (bn0 + 64 <= bm0) return;   // no gj >= gi elements in this tile

    __shared__ float As[16][128];
    __shared__ float Bs[16][64];

    int tid = threadIdx.x;
    int tx = tid & 7, ty = tid >> 3;
    int a_r = tid >> 2, a_k = (tid & 3) * 4;   // A loader (rows +=32, 4 passes)
    int b_r = tid >> 1, b_k = (tid & 1) * 8;   // B loader: 64 rows x 8 k each

    u64 acc[8][4];
#pragma unroll
    for (int i = 0; i < 8; i++)
#pragma unroll
        for (int j = 0; j < 4; j++) acc[i][j] = 0ull;

    for (int k0 = 0; k0 < DIM; k0 += 16) {
#pragma unroll
        for (int p = 0; p < 4; p++) {
            int gm = bm0 + a_r + 32 * p;
            float4 v = make_float4(0.f, 0.f, 0.f, 0.f);
            if (gm < n) v = *reinterpret_cast<const float4*>(X + (size_t)gm * DIM + k0 + a_k);
            int r = a_r + 32 * p;
            As[a_k + 0][r] = v.x; As[a_k + 1][r] = v.y;
            As[a_k + 2][r] = v.z; As[a_k + 3][r] = v.w;
        }
        {
            int gn = bn0 + b_r;
            float4 v0 = make_float4(0.f, 0.f, 0.f, 0.f), v1 = v0;
            if (gn < n) {
                v0 = *reinterpret_cast<const float4*>(X + (size_t)gn * DIM + k0 + b_k);
                v1 = *reinterpret_cast<const float4*>(X + (size_t)gn * DIM + k0 + b_k + 4);
            }
            Bs[b_k + 0][b_r] = v0.x; Bs[b_k + 1][b_r] = v0.y;
            Bs[b_k + 2][b_r] = v0.z; Bs[b_k + 3][b_r] = v0.w;
            Bs[b_k + 4][b_r] = v1.x; Bs[b_k + 5][b_r] = v1.y;
            Bs[b_k + 6][b_r] = v1.z; Bs[b_k + 7][b_r] = v1.w;
        }
        __syncthreads();
#pragma unroll
        for (int kk = 0; kk < 16; kk++) {
            ulonglong2 b01 = *reinterpret_cast<const ulonglong2*>(&Bs[kk][tx * 8]);
            ulonglong2 b23 = *reinterpret_cast<const ulonglong2*>(&Bs[kk][tx * 8 + 4]);
            float4 a03 = *reinterpret_cast<const float4*>(&As[kk][ty * 8]);
            float4 a47 = *reinterpret_cast<const float4*>(&As[kk][ty * 8 + 4]);
            u64 ad0 = dup2(a03.x), ad1 = dup2(a03.y), ad2 = dup2(a03.z), ad3 = dup2(a03.w);
            u64 ad4 = dup2(a47.x), ad5 = dup2(a47.y), ad6 = dup2(a47.z), ad7 = dup2(a47.w);
            ffma2(acc[0][0], ad0, b01.x); ffma2(acc[0][1], ad0, b01.y);
            ffma2(acc[0][2], ad0, b23.x); ffma2(acc[0][3], ad0, b23.y);
            ffma2(acc[1][0], ad1, b01.x); ffma2(acc[1][1], ad1, b01.y);
            ffma2(acc[1][2], ad1, b23.x); ffma2(acc[1][3], ad1, b23.y);
            ffma2(acc[2][0], ad2, b01.x); ffma2(acc[2][1], ad2, b01.y);
            ffma2(acc[2][2], ad2, b23.x); ffma2(acc[2][3], ad2, b23.y);
            ffma2(acc[3][0], ad3, b01.x); ffma2(acc[3][1], ad3, b01.y);
            ffma2(acc[3][2], ad3, b23.x); ffma2(acc[3][3], ad3, b23.y);
            ffma2(acc[4][0], ad4, b01.x); ffma2(acc[4][1], ad4, b01.y);
            ffma2(acc[4][2], ad4, b23.x); ffma2(acc[4][3], ad4, b23.y);
            ffma2(acc[5][0], ad5, b01.x); ffma2(acc[5][1], ad5, b01.y);
            ffma2(acc[5][2], ad5, b23.x); ffma2(acc[5][3], ad5, b23.y);
            ffma2(acc[6][0], ad6, b01.x); ffma2(acc[6][1], ad6, b01.y);
            ffma2(acc[6][2], ad6, b23.x); ffma2(acc[6][3], ad6, b23.y);
            ffma2(acc[7][0], ad7, b01.x); ffma2(acc[7][1], ad7, b01.y);
            ffma2(acc[7][2], ad7, b23.x); ffma2(acc[7][3], ad7, b23.y);
        }
        __syncthreads();
    }

#pragma unroll
    for (int i = 0; i < 8; i++) {
        int gi = bm0 + ty * 8 + i;
        if (gi >= n) continue;
        float f[8];
        *reinterpret_cast<ulonglong2*>(&f[0]) = *reinterpret_cast<ulonglong2*>(&acc[i][0]);
        *reinterpret_cast<ulonglong2*>(&f[4]) = *reinterpret_cast<ulonglong2*>(&acc[i][2]);
#pragma unroll
        for (int j = 0; j < 8; j++) {
            int gj = bn0 + tx * 8 + j;
            if (gj < n && gj >= gi) {
                float v = (gi == gj) ? 1.0f : f[j];
                out[(size_t)gi * n + gj] = v;
                out[(size_t)gj * n + gi] = v;
            }
        }
    }
}

// ---------------- gather materialization of sub-adjacency --------------------
__global__ void gatherA(float* __restrict__ dst, int ldd,
                        const float* __restrict__ A,
                        const int* __restrict__ ridx, const int* __restrict__ cidx,
                        int M, int Ksub, int Kpad)
{
    int k = blockIdx.x * 256 + threadIdx.x;
    int m = blockIdx.y;
    if (k >= Kpad || m >= M) return;
    float v = 0.f;
    if (k < Ksub) {
        int r = ridx ? ridx[m] : m;
        v = __ldg(&A[(size_t)r * NN + cidx[k]]);
    }
    dst[(size_t)m * ldd + k] = v;
}

// ---------------- bias + ReLU (+residual); sums 4 k-slices -------------------
__global__ void epilogue(const float* __restrict__ T, long long sliceT,
                         const float* __restrict__ bias, const float* __restrict__ R,
                         float* __restrict__ d1, int ld1,
                         float* __restrict__ d2, int ld2, int n)
{
    int i = blockIdx.x * blockDim.x + threadIdx.x;
    if (i >= n * DIM) return;
    int r = i / DIM, c = i - r * DIM;
    float v = T[i] + T[i + sliceT] + T[i + 2 * sliceT] + T[i + 3 * sliceT] + bias[c];
    v = v > 0.f ? v : 0.f;
    if (R) v += R[i];
    d1[(size_t)r * ld1 + c] = v;
    if (d2) d2[(size_t)r * ld2 + c] = v;
}

// ---------------- pooling scores: sigmoid((X . pw + pb)/100) -----------------
__global__ void scores_kernel(const float* __restrict__ X, int n,
                              const float* __restrict__ pw, const float* __restrict__ pb,
                              float* __restrict__ out)
{
    int row = blockIdx.x * 8 + (threadIdx.x >> 5);
    int lane = threadIdx.x & 31;
    if (row >= n) return;
    float s = 0.f;
    for (int c = lane; c < DIM; c += 32) s += X[(size_t)row * DIM + c] * pw[c];
#pragma unroll
    for (int o = 16; o > 0; o >>= 1) s += __shfl_down_sync(0xffffffffu, s, o);
    if (lane == 0) {
        float z = (s + pb[0]) * 0.01f;
        out[row] = 1.0f / (1.0f + expf(-z));
    }
}

// ---------------- exact top-k via full bitonic sort (desc score, asc idx) ----
__global__ void topk_sort(const float* __restrict__ scores, int n,
                          int* __restrict__ idx_out, float* __restrict__ val_out)
{
    __shared__ unsigned long long keys[4096];
    int tid = threadIdx.x;  // 1024 threads
    for (int i = tid; i < 4096; i += 1024) {
        unsigned long long k = 0ull;
        if (i < n) {
            unsigned int fb = __float_as_uint(scores[i]);
            k = ((unsigned long long)fb << 12) | (unsigned int)(4095 - i);
        }
        keys[i] = k;
    }
    __syncthreads();
    for (int k = 2; k <= 4096; k <<= 1) {
        for (int j = k >> 1; j > 0; j >>= 1) {
            for (int t = tid; t < 4096; t += 1024) {
                int ixj = t ^ j;
                if (ixj > t) {
                    bool desc = ((t & k) == 0);
                    unsigned long long a = keys[t], b = keys[ixj];
                    if ((a < b) == desc) { keys[t] = b; keys[ixj] = a; }
                }
            }
            __syncthreads();
        }
    }
    for (int i = tid; i < 4096; i += 1024) {
        unsigned long long kk = keys[i];
        idx_out[i] = 4095 - (int)(kk & 0xFFFull);
        val_out[i] = __uint_as_float((unsigned int)(kk >> 12));
    }
}

__global__ void gather_scale(const float* __restrict__ X, const int* __restrict__ idx,
                             const float* __restrict__ vals, float* __restrict__ out, int kn)
{
    int i = blockIdx.x * 256 + threadIdx.x;
    if (i >= kn * DIM) return;
    int r = i / DIM, c = i - r * DIM;
    out[i] = X[(size_t)idx[r] * DIM + c] * vals[r];
}

__global__ void compose_idx(const int* __restrict__ a, const int* __restrict__ b,
                            int* __restrict__ out, int n)
{
    int i = blockIdx.x * 256 + threadIdx.x;
    if (i < n) out[i] = a[b[i]];
}

// -----------------------------------------------------------------------------
extern "C" void kernel_launch(void* const* d_in, const int* in_sizes, int n_in,
                              void* d_out, int out_size)
{
    const float* A       = (const float*)d_in[0];
    const float* X       = (const float*)d_in[1];
    const float* w_start = (const float*)d_in[2];  const float* b_start  = (const float*)d_in[3];
    const float* w_down0 = (const float*)d_in[4];  const float* b_down0  = (const float*)d_in[5];
    const float* w_down1 = (const float*)d_in[6];  const float* b_down1  = (const float*)d_in[7];
    const float* p_w0    = (const float*)d_in[8];  const float* p_b0     = (const float*)d_in[9];
    const float* p_w1    = (const float*)d_in[10]; const float* p_b1     = (const float*)d_in[11];
    const float* w_bottom= (const float*)d_in[12]; const float* b_bottom = (const float*)d_in[13];
    const float* w_up0   = (const float*)d_in[14]; const float* b_up0    = (const float*)d_in[15];
    const float* w_up1   = (const float*)d_in[16]; const float* b_up1    = (const float*)d_in[17];
    const float* w_end   = (const float*)d_in[18]; const float* b_end    = (const float*)d_in[19];
    float* out = (float*)d_out;

    float *P, *Q, *AXp, *X0, *Xd0, *Xp0, *Xd1, *Xp1, *Xb, *Xu, *Xcat;
    float *AB1, *AB2, *ABu0, *ABu1, *sc, *v0, *v1;
    int *i0, *i1, *i01;
    cudaGetSymbolAddress((void**)&P,    g_P);
    cudaGetSymbolAddress((void**)&Q,    g_Q);
    cudaGetSymbolAddress((void**)&AXp,  g_AXp);
    cudaGetSymbolAddress((void**)&X0,   g_X0);
    cudaGetSymbolAddress((void**)&Xd0,  g_Xd0);
    cudaGetSymbolAddress((void**)&Xp0,  g_Xp0);
    cudaGetSymbolAddress((void**)&Xd1,  g_Xd1);
    cudaGetSymbolAddress((void**)&Xp1,  g_Xp1);
    cudaGetSymbolAddress((void**)&Xb,   g_Xb);
    cudaGetSymbolAddress((void**)&Xu,   g_Xu);
    cudaGetSymbolAddress((void**)&Xcat, g_Xcat);
    cudaGetSymbolAddress((void**)&AB1,  g_AB1);
    cudaGetSymbolAddress((void**)&AB2,  g_AB2);
    cudaGetSymbolAddress((void**)&ABu0, g_ABu0);
    cudaGetSymbolAddress((void**)&ABu1, g_ABu1);
    cudaGetSymbolAddress((void**)&sc,   g_scores);
    cudaGetSymbolAddress((void**)&i0,   g_idx0);
    cudaGetSymbolAddress((void**)&v0,   g_val0);
    cudaGetSymbolAddress((void**)&i1,   g_idx1);
    cudaGetSymbolAddress((void**)&v1,   g_val1);
    cudaGetSymbolAddress((void**)&i01,  g_idx01);

    const long long PS  = (long long)NN * DIM;       // P/Q slice stride
    const long long PSX = (long long)NN * 2 * DIM;   // AXp slice stride

    auto launchG = [](const float* A_, long long sliceA_, int nSl_, int lda_,
                      const float* B_, int ldb_,
                      float* C_, int ldc_, long long pstride_,
                      int M_, int N_, int K_) {
        int kChunk = (((K_ + 3) / 4 + 15) / 16) * 16;
        dim3 g((unsigned)(N_ / 64), (unsigned)((M_ + 127) / 128), 4);
        gemmBig<<<g, 128>>>(A_, sliceA_, nSl_, lda_, B_, ldb_, C_, ldc_, pstride_,
                            M_, kChunk, K_);
    };
    auto eg = [](int n) { return (unsigned)((n * DIM + 255) / 256); };

    // ---- start: X0 = relu((A@X)@w_start + b); -> out_start, Xcat right half
    launchG(A, 0, 1, NN, X, DIM, P, DIM, PS, NN, DIM, NN);
    launchG(P, PS, 4, DIM, w_start, DIM, Q, DIM, PS, NN, DIM, DIM);
    epilogue<<<eg(NN), 256>>>(Q, PS, b_start, nullptr, X0, DIM, Xcat + DIM, 2 * DIM, NN);
    cudaMemcpyAsync(out + OFF_START, X0, (size_t)NN * DIM * sizeof(float),
                    cudaMemcpyDeviceToDevice, 0);

    // ---- Xd0 = gcn(A, X0, w_down0); A@X0 slices kept in AXp right half (end reuse)
    launchG(A, 0, 1, NN, X0, DIM, AXp + DIM, 2 * DIM, PSX, NN, DIM, NN);
    launchG(AXp + DIM, PSX, 4, 2 * DIM, w_down0, DIM, Q, DIM, PS, NN, DIM, DIM);
    epilogue<<<eg(NN), 256>>>(Q, PS, b_down0, nullptr, Xd0, DIM, nullptr, 0, NN);

    // ---- pool 0
    scores_kernel<<<(NN + 7) / 8, 256>>>(Xd0, NN, p_w0, p_b0, sc);
    topk_sort<<<1, 1024>>>(sc, NN, i0, v0);
    gather_scale<<<(KP0 * DIM + 255) / 256, 256>>>(Xd0, i0, v0, Xp0, KP0);
    gatherA<<<dim3((KP0P + 255) / 256, KP0), 256>>>(AB1, KP0P, A, i0, i0, KP0, KP0, KP0P);
    gatherA<<<dim3((KP0P + 255) / 256, NN), 256>>>(ABu1, KP0P, A, nullptr, i0, NN, KP0, KP0P);

    // ---- Xd1 = gcn(A1, Xp0, w_down1)
    launchG(AB1, 0, 1, KP0P, Xp0, DIM, P, DIM, PS, KP0, DIM, KP0P);
    launchG(P, PS, 4, DIM, w_down1, DIM, Q, DIM, PS, KP0, DIM, DIM);
    epilogue<<<eg(KP0), 256>>>(Q, PS, b_down1, nullptr, Xd1, DIM, nullptr, 0, KP0);

    // ---- pool 1
    scores_kernel<<<(KP0 + 7) / 8, 256>>>(Xd1, KP0, p_w1, p_b1, sc);
    topk_sort<<<1, 1024>>>(sc, KP0, i1, v1);
    gather_scale<<<(KP1 * DIM + 255) / 256, 256>>>(Xd1, i1, v1, Xp1, KP1);
    compose_idx<<<(KP1 + 255) / 256, 256>>>(i0, i1, i01, KP1);
    gatherA<<<dim3((KP1P + 255) / 256, KP1), 256>>>(AB2, KP1P, A, i01, i01, KP1, KP1, KP1P);
    gatherA<<<dim3((KP1P + 255) / 256, KP0), 256>>>(ABu0, KP1P, A, i0, i01, KP0, KP1, KP1P);

    // ---- bottom: Xb = gcn(A2, Xp1, w_bottom)
    launchG(AB2, 0, 1, KP1P, Xp1, DIM, P, DIM, PS, KP1, DIM, KP1P);
    launchG(P, PS, 4, DIM, w_bottom, DIM, Q, DIM, PS, KP1, DIM, DIM);
    epilogue<<<eg(KP1), 256>>>(Q, PS, b_bottom, nullptr, Xb, DIM, nullptr, 0, KP1);

    // ---- up 0: Xu = gcn(A1, scatter(Xb), w_up0) + Xd1
    launchG(ABu0, 0, 1, KP1P, Xb, DIM, P, DIM, PS, KP0, DIM, KP1P);
    launchG(P, PS, 4, DIM, w_up0, DIM, Q, DIM, PS, KP0, DIM, DIM);
    epilogue<<<eg(KP0), 256>>>(Q, PS, b_up0, Xd1, Xu, DIM, nullptr, 0, KP0);

    // ---- up 1: Xu2 = gcn(A, scatter(Xu), w_up1) + Xd0 -> Xcat left half
    launchG(ABu1, 0, 1, KP0P, Xu, DIM, P, DIM, PS, NN, DIM, KP0P);
    launchG(P, PS, 4, DIM, w_up1, DIM, Q, DIM, PS, NN, DIM, DIM);
    epilogue<<<eg(NN), 256>>>(Q, PS, b_up1, Xd0, Xcat, 2 * DIM, nullptr, 0, NN);

    // ---- end: Xout = gcn(A, Xcat, w_end); A@X0 (right half of A@Xcat) reused
    launchG(A, 0, 1, NN, Xcat, 2 * DIM, AXp, 2 * DIM, PSX, NN, DIM, NN);
    launchG(AXp, PSX, 4, 2 * DIM, w_end, DIM, Q, DIM, PS, NN, DIM, 2 * DIM);
    epilogue<<<eg(NN), 256>>>(Q, PS, b_end, nullptr, out, DIM, nullptr, 0, NN);

    // ---- pool_out = Xp0 @ Xp0^T (triangular + mirror), diag = 1
    pool_gemm<<<dim3((KP0 + 63) / 64, (KP0 + 127) / 128), 128>>>(Xp0, out + OFF_POOL, KP0);
}